// round 2
// baseline (speedup 1.0000x reference)
#include <cuda_runtime.h>
#include <cuda_bf16.h>
#include <math.h>

#define THREADS 256

// Padded shared-memory strides (in floats). Chosen so that the 3 weight sets
// sit at bank offsets {0, 8, 16}: a warp with mixed labels issues <=3 distinct
// 16B shared loads per LDS.128, all in disjoint bank groups -> 1 phase.
#define S1  1288   // 20*64 + 8
#define SB1 72     // 64 + 8
#define S2  200    // 3*64 + 8
#define SB2 4

__device__ __forceinline__ unsigned long long fma2(unsigned long long a,
                                                   unsigned long long b,
                                                   unsigned long long c) {
    unsigned long long d;
    asm("fma.rn.f32x2 %0, %1, %2, %3;" : "=l"(d) : "l"(a), "l"(b), "l"(c));
    return d;
}
__device__ __forceinline__ unsigned long long pack2(float a, float b) {
    unsigned long long r;
    asm("mov.b64 %0, {%1, %2};" : "=l"(r) : "f"(a), "f"(b));
    return r;
}
__device__ __forceinline__ void unpack2(unsigned long long v, float& a, float& b) {
    asm("mov.b64 {%0, %1}, %2;" : "=f"(a), "=f"(b) : "l"(v));
}

// tanh(x) = sign(x) * (1 - e) / (1 + e), e = exp(-2|x|).
// ex2.approx rel err ~2^-22; far more accurate than tanh.approx, ~5 ops.
__device__ __forceinline__ float tanh_fast(float x) {
    float ax = fabsf(x);
    float e;
    asm("ex2.approx.f32 %0, %1;" : "=f"(e) : "f"(ax * -2.8853900817779268f));
    float r = __fdividef(1.0f - e, 1.0f + e);
    return copysignf(r, x);
}

__global__ void __launch_bounds__(THREADS, 2)
rs_kernel(const float* __restrict__ P, const float* __restrict__ U,
          const float* __restrict__ F,
          const float* __restrict__ cmax, const float* __restrict__ cmin,
          const float* __restrict__ W1_ds, const float* __restrict__ b1_ds,
          const float* __restrict__ W2_ds, const float* __restrict__ b2_ds,
          const float* __restrict__ W1_dr, const float* __restrict__ b1_dr,
          const float* __restrict__ W2_dr, const float* __restrict__ b2_dr,
          const float* __restrict__ W1_rs, const float* __restrict__ b1_rs,
          const float* __restrict__ W2_rs, const float* __restrict__ b2_rs,
          float* __restrict__ out, int N)
{
    __shared__ __align__(16) float sm[3 * S1 + 3 * SB1 + 3 * S2 + 3 * SB2];
    float* w1s = sm;
    float* b1s = sm + 3 * S1;
    float* w2s = b1s + 3 * SB1;
    float* b2s = w2s + 3 * S2;

    {
        const float* w1p[3] = {W1_ds, W1_dr, W1_rs};
        const float* b1p[3] = {b1_ds, b1_dr, b1_rs};
        const float* w2p[3] = {W2_ds, W2_dr, W2_rs};
        const float* b2p[3] = {b2_ds, b2_dr, b2_rs};
        #pragma unroll
        for (int m = 0; m < 3; m++) {
            for (int i = threadIdx.x; i < 1280; i += THREADS) w1s[m * S1 + i] = w1p[m][i];
            for (int i = threadIdx.x; i < 64; i += THREADS)   b1s[m * SB1 + i] = b1p[m][i];
            // W2 stored transposed: [j][h] so layer-2 dots are contiguous over h
            for (int i = threadIdx.x; i < 192; i += THREADS) {
                int h = i / 3, j = i % 3;
                w2s[m * S2 + j * 64 + h] = w2p[m][i];
            }
            if (threadIdx.x < 3) b2s[m * SB2 + threadIdx.x] = b2p[m][threadIdx.x];
        }
    }
    __syncthreads();

    int n = blockIdx.x * THREADS + threadIdx.x;
    if (n >= N) return;

    const float2* P2 = reinterpret_cast<const float2*>(P + (size_t)n * 6);
    const float2* U2 = reinterpret_cast<const float2*>(U + (size_t)n * 6);
    const float2* F2 = reinterpret_cast<const float2*>(F + (size_t)n * 6);
    float2 p0 = P2[0], p1 = P2[1], p2 = P2[2];
    float2 u0 = U2[0], u1 = U2[1], u2 = U2[2];
    float2 f0 = F2[0], f1 = F2[1], f2 = F2[2];
    float cm = cmax[n], cn = cmin[n];

    // flip: swap left/right states; sgn = (1,1,-1) for P,U; (-1,-1,1) for F
    bool flip = p1.y > p1.x;
    if (flip) {
        float t;
        t = p0.x; p0.x = p0.y;  p0.y = t;
        t = p1.x; p1.x = p1.y;  p1.y = t;
        t = p2.x; p2.x = -p2.y; p2.y = -t;
        t = u0.x; u0.x = u0.y;  u0.y = t;
        t = u1.x; u1.x = u1.y;  u1.y = t;
        t = u2.x; u2.x = -u2.y; u2.y = -t;
        t = f0.x; f0.x = -f0.y; f0.y = -t;
        t = f1.x; f1.x = -f1.y; f1.y = -t;
        t = f2.x; f2.x = f2.y;  f2.y = t;
    }

    // contact detection
    float d0 = fabsf(p0.y - p0.x), d1 = fabsf(p1.y - p1.x), d2 = fabsf(p2.y - p2.x);
    bool cont = fmaxf(d0, fmaxf(d1, d2)) < 0.005f;

    // HLLE flux
    float inv = 1.0f / (cm - cn);
    float cmcn = cm * cn;
    float h0 = (cm * f0.x - cn * f0.y + cmcn * (u0.y - u0.x)) * inv;
    float h1 = (cm * f1.x - cn * f1.y + cmcn * (u1.y - u1.x)) * inv;
    float h2 = (cm * f2.x - cn * f2.y + cmcn * (u2.y - u2.x)) * inv;

    // classify (gamma = 5/3: z = 0.2, 1/z = 5, 2/(g-1) = 3, (g-1)/2 = 1/3)
    const float G = 5.0f / 3.0f;
    float c0 = sqrtf(G * p1.x / p0.x);
    float c1 = sqrtf(G * p1.y / p0.y);
    float dv = p2.y - p2.x;
    float num = (c0 + c1) - (1.0f / 3.0f) * dv;
    float den = c0 * __powf(p1.x, -0.2f) + c1 * __powf(p1.y, -0.2f);
    float ps = fmaxf(num / den, 1e-8f);
    float ps2 = ps * ps;
    float p_star = ps2 * ps2 * ps;
    bool vac = dv >= 3.0f * (c0 + c1);
    bool dsb = p_star > fmaxf(p1.x, p1.y);
    bool drb = p_star < fminf(p1.x, p1.y);
    int label = vac ? 3 : (drb ? 1 : (dsb ? 0 : 2));

    float o0 = 0.0f, o1 = 0.0f, o2 = 0.0f;

    if (!cont && label < 3) {
        float feats[20] = {p0.x, p0.y, p1.x, p1.y, p2.x, p2.y,
                           u0.x, u0.y, u1.x, u1.y, u2.x, u2.y,
                           f0.x, f0.y, f1.x, f1.y, f2.x, f2.y,
                           cm, cn};
        // label 0->ds, 1->dr, 2->rs == smem order
        const float* w1 = w1s + label * S1;
        const unsigned long long* b1v =
            reinterpret_cast<const unsigned long long*>(b1s + label * SB1);

        unsigned long long acc[32];
        #pragma unroll
        for (int i = 0; i < 32; i++) acc[i] = b1v[i];

        #pragma unroll
        for (int k = 0; k < 20; k++) {
            unsigned long long xk2 = pack2(feats[k], feats[k]);
            const ulonglong2* row = reinterpret_cast<const ulonglong2*>(w1 + k * 64);
            #pragma unroll
            for (int i = 0; i < 16; i++) {
                ulonglong2 w = row[i];
                acc[2 * i]     = fma2(xk2, w.x, acc[2 * i]);
                acc[2 * i + 1] = fma2(xk2, w.y, acc[2 * i + 1]);
            }
        }

        #pragma unroll
        for (int i = 0; i < 32; i++) {
            float a, b;
            unpack2(acc[i], a, b);
            acc[i] = pack2(tanh_fast(a), tanh_fast(b));
        }

        const float* w2 = w2s + label * S2;
        float ojs[3];
        #pragma unroll
        for (int j = 0; j < 3; j++) {
            const ulonglong2* row = reinterpret_cast<const ulonglong2*>(w2 + j * 64);
            unsigned long long a0 = pack2(0.0f, 0.0f);
            unsigned long long a1 = pack2(0.0f, 0.0f);
            #pragma unroll
            for (int i = 0; i < 16; i++) {
                ulonglong2 w = row[i];
                a0 = fma2(acc[2 * i],     w.x, a0);
                a1 = fma2(acc[2 * i + 1], w.y, a1);
            }
            float x0, x1, x2, x3;
            unpack2(a0, x0, x1);
            unpack2(a1, x2, x3);
            ojs[j] = ((x0 + x1) + (x2 + x3)) + b2s[label * SB2 + j];
        }
        o0 = ojs[0]; o1 = ojs[1]; o2 = ojs[2];
    }

    if (cont) { o0 = h0; o1 = h1; o2 = h2; }
    if (flip) { o0 = -o0; o1 = -o1; }  // flux * (-sgn) = (-1,-1,1)

    out[(size_t)n * 3 + 0] = o0;
    out[(size_t)n * 3 + 1] = o1;
    out[(size_t)n * 3 + 2] = o2;
}

extern "C" void kernel_launch(void* const* d_in, const int* in_sizes, int n_in,
                              void* d_out, int out_size) {
    const float* P     = (const float*)d_in[0];
    const float* U     = (const float*)d_in[1];
    const float* F     = (const float*)d_in[2];
    const float* cmax  = (const float*)d_in[3];
    const float* cmin  = (const float*)d_in[4];
    const float* W1_ds = (const float*)d_in[5];
    const float* b1_ds = (const float*)d_in[6];
    const float* W2_ds = (const float*)d_in[7];
    const float* b2_ds = (const float*)d_in[8];
    const float* W1_dr = (const float*)d_in[9];
    const float* b1_dr = (const float*)d_in[10];
    const float* W2_dr = (const float*)d_in[11];
    const float* b2_dr = (const float*)d_in[12];
    const float* W1_rs = (const float*)d_in[13];
    const float* b1_rs = (const float*)d_in[14];
    const float* W2_rs = (const float*)d_in[15];
    const float* b2_rs = (const float*)d_in[16];

    int N = in_sizes[3];  // cmax element count == N_CELLS
    int blocks = (N + THREADS - 1) / THREADS;
    rs_kernel<<<blocks, THREADS>>>(P, U, F, cmax, cmin,
                                   W1_ds, b1_ds, W2_ds, b2_ds,
                                   W1_dr, b1_dr, W2_dr, b2_dr,
                                   W1_rs, b1_rs, W2_rs, b2_rs,
                                   (float*)d_out, N);
}